// round 10
// baseline (speedup 1.0000x reference)
#include <cuda_runtime.h>
#include <math.h>

#define NN 4096
#define NF 4096
#define NH 4
#define NO 8
#define NC32 32            // NH*NO
#define NW (NN/32)         // bitmask words per row = 128
#define JS 64              // attention j-splits (grid.y): 64 j per block
#define GKS 32             // k-splits for gemm
#define GAT_ALPHA 0.2f
#define L2E 1.44269504088896341f
#define KA  0.28853900817792683f   // 0.2 * log2(e)

// ---------------- scratch (__device__ globals; no allocations) ----------------
__device__ float         g_Cpart[GKS][NN * NC32]; // k-split GEMM partials (16MB)
__device__ float         g_Wh[NN * NC32];         // Wh interleaved: [i*32 + hp*16 + o*2 + (h&1)]
__device__ float         g_sdst4[NN * NH];        // s_dst[j][h]
__device__ float         g_ssrc4[NN * NH];        // s_src[i][h]
__device__ unsigned      g_bmT[NW * NN];          // bitmask: word g*4+q, bit l <-> j=g*128+4l+q
__device__ unsigned      g_maxsd[NH];             // global max of s_dst per head (keyed)
__device__ float         g_hp[NN * NC32];         // red-accumulated h' numerator (1MB)
__device__ float         g_z[NN * NH];            // red-accumulated Z
__device__ float         g_ls[NN * NO];           // log_softmax(node_embeddings)

// ---------------- helpers ----------------
__device__ __forceinline__ void ffma2(unsigned long long& d, unsigned long long a,
                                      unsigned long long b) {
    asm("fma.rn.f32x2 %0, %1, %2, %0;" : "+l"(d) : "l"(a), "l"(b));
}
__device__ __forceinline__ void addf2(unsigned long long& d, unsigned long long a) {
    asm("add.rn.f32x2 %0, %0, %1;" : "+l"(d) : "l"(a));
}
__device__ __forceinline__ unsigned long long packab(float a, float b) {
    unsigned long long r;
    asm("mov.b64 %0, {%1, %2};" : "=l"(r) : "f"(a), "f"(b));
    return r;
}
__device__ __forceinline__ float ex2f(float x) {
    float r;
    asm("ex2.approx.ftz.f32 %0, %1;" : "=f"(r) : "f"(x));
    return r;
}
__device__ __forceinline__ void red4(float* p, float a, float b, float c, float d) {
    asm volatile("red.global.add.v4.f32 [%0], {%1, %2, %3, %4};"
                 :: "l"(p), "f"(a), "f"(b), "f"(c), "f"(d) : "memory");
}
union U64F2 { unsigned long long u; float2 f; };

__device__ __forceinline__ unsigned fkey(float f) {
    unsigned u = __float_as_uint(f);
    return (u & 0x80000000u) ? ~u : (u | 0x80000000u);
}
__device__ __forceinline__ float funkey(unsigned k) {
    return __uint_as_float((k & 0x80000000u) ? (k & 0x7FFFFFFFu) : ~k);
}

// ---------------- 1) pack adjacency (int4 + 4 ballots, permuted bits) ----------------
// grid 1024 x 128.  word g*4+q, bit l  <->  adj[i][g*128 + l*4 + q]
__global__ void k_pack(const int* __restrict__ adj) {
    int t = threadIdx.x;
    int gt = blockIdx.x * 128 + t;                    // 1024*128 = NN*NC32
    g_hp[gt] = 0.f;
    if (gt < NN * NH) g_z[gt] = 0.f;
    if (gt < NH) g_maxsd[gt] = 0u;

    int w = t >> 5, lane = t & 31;
    int i = blockIdx.x * 4 + w;
    const int4* row = (const int4*)(adj + (size_t)i * NN);
#pragma unroll 8
    for (int g = 0; g < 32; g++) {                    // 32 groups of 128 j
        int4 v = __ldg(row + g * 32 + lane);          // j = g*128 + lane*4 + {0..3}
        unsigned b0 = __ballot_sync(0xffffffffu, v.x != 0);
        unsigned b1 = __ballot_sync(0xffffffffu, v.y != 0);
        unsigned b2 = __ballot_sync(0xffffffffu, v.z != 0);
        unsigned b3 = __ballot_sync(0xffffffffu, v.w != 0);
        if (lane == 0) {
            g_bmT[(size_t)(g * 4 + 0) * NN + i] = b0;
            g_bmT[(size_t)(g * 4 + 1) * NN + i] = b1;
            g_bmT[(size_t)(g * 4 + 2) * NN + i] = b2;
            g_bmT[(size_t)(g * 4 + 3) * NN + i] = b3;
        }
    }
}

// ---------------- 2) Wh = x @ Wc  (BM=128, duplicated-x smem, k-split x32) ----------------
// Thread (rg = t>>3, c4g = t&7) owns rows {rg + 32*rr} (rr<4), cols c4g*4..+3.
__global__ void __launch_bounds__(256) k_gemm(const float* __restrict__ x,
                                              const float* __restrict__ W) {
    __shared__ __align__(16) float2 xs2[128 * 34];  // (v,v) per k, stride 34
    __shared__ float ws[32][36];
    int t = threadIdx.x;
    int c4g = t & 7;
    int rg = t >> 3;           // 0..31
    int row0 = blockIdx.x * 128;
    int kbase = blockIdx.y * (NF / GKS);   // 128 k per block

    unsigned long long acc01[4], acc23[4];
#pragma unroll
    for (int r = 0; r < 4; r++) { acc01[r] = 0ull; acc23[r] = 0ull; }

    for (int kt = 0; kt < NF / GKS; kt += 32) {
        int k0 = kbase + kt;
#pragma unroll
        for (int q = 0; q < 4; q++) {
            int f = q * 256 + t;
            int row = f >> 3, kq = f & 7;
            float4 v = __ldg((const float4*)(x + (size_t)(row0 + row) * NF + k0 + kq * 4));
            *(float4*)&xs2[row * 34 + kq * 4]     = make_float4(v.x, v.x, v.y, v.y);
            *(float4*)&xs2[row * 34 + kq * 4 + 2] = make_float4(v.z, v.z, v.w, v.w);
        }
        {
            int k = t >> 3, c4 = (t & 7) * 4;
            int h = c4 >> 3, o = c4 & 7;
            float4 v = __ldg((const float4*)(W + (size_t)h * NF * NO + (size_t)(k0 + k) * NO + o));
            *(float4*)&ws[k][c4] = v;
        }
        __syncthreads();
#pragma unroll
        for (int kk = 0; kk < 8; kk++) {
            float4 w0 = *(const float4*)&ws[kk * 4 + 0][c4g * 4];
            float4 w1 = *(const float4*)&ws[kk * 4 + 1][c4g * 4];
            float4 w2 = *(const float4*)&ws[kk * 4 + 2][c4g * 4];
            float4 w3 = *(const float4*)&ws[kk * 4 + 3][c4g * 4];
            unsigned long long w01_0 = packab(w0.x, w0.y), w23_0 = packab(w0.z, w0.w);
            unsigned long long w01_1 = packab(w1.x, w1.y), w23_1 = packab(w1.z, w1.w);
            unsigned long long w01_2 = packab(w2.x, w2.y), w23_2 = packab(w2.z, w2.w);
            unsigned long long w01_3 = packab(w3.x, w3.y), w23_3 = packab(w3.z, w3.w);
#pragma unroll
            for (int rr = 0; rr < 4; rr++) {
                int row = rg + rr * 32;
                ulonglong2 xv01 = *(const ulonglong2*)&xs2[row * 34 + kk * 4];
                ulonglong2 xv23 = *(const ulonglong2*)&xs2[row * 34 + kk * 4 + 2];
                ffma2(acc01[rr], xv01.x, w01_0); ffma2(acc23[rr], xv01.x, w23_0);
                ffma2(acc01[rr], xv01.y, w01_1); ffma2(acc23[rr], xv01.y, w23_1);
                ffma2(acc01[rr], xv23.x, w01_2); ffma2(acc23[rr], xv23.x, w23_2);
                ffma2(acc01[rr], xv23.y, w01_3); ffma2(acc23[rr], xv23.y, w23_3);
            }
        }
        __syncthreads();
    }
    float* outp = g_Cpart[blockIdx.y];
#pragma unroll
    for (int rr = 0; rr < 4; rr++) {
        U64F2 a, b; a.u = acc01[rr]; b.u = acc23[rr];
        *(float4*)&outp[(size_t)(row0 + rg + rr * 32) * NC32 + c4g * 4] =
            make_float4(a.f.x, a.f.y, b.f.x, b.f.y);
    }
}

// ---------------- 3) reduce k-splits; interleaved Wh; s_src/s_dst; sd max ----------------
// grid 256 x 128: 16 rows per block
__global__ void k_whfin(const float* __restrict__ av) {
    __shared__ float sm[16][36];
    int t = threadIdx.x;
    int rl = t >> 3;          // local row 0..15
    int c4 = t & 7;           // float4 column group
    int i = blockIdx.x * 16 + rl;

    float4 s = make_float4(0.f, 0.f, 0.f, 0.f);
#pragma unroll
    for (int ks = 0; ks < GKS; ks++) {
        float4 p = *(const float4*)&g_Cpart[ks][(size_t)i * NC32 + c4 * 4];
        s.x += p.x; s.y += p.y; s.z += p.z; s.w += p.w;
    }
    *(float4*)&sm[rl][c4 * 4] = s;
    __syncthreads();

    // interleaved Wh write
    {
        int hp = c4 >> 2, k4 = c4 & 3;
        float4 o;
        o.x = sm[rl][hp * 16 + 2 * k4];
        o.y = sm[rl][hp * 16 + 8 + 2 * k4];
        o.z = sm[rl][hp * 16 + 2 * k4 + 1];
        o.w = sm[rl][hp * 16 + 8 + 2 * k4 + 1];
        *(float4*)&g_Wh[(size_t)i * NC32 + hp * 16 + k4 * 4] = o;
    }

    if (t < 16) {
        int ii = blockIdx.x * 16 + t;
        float ssv[4], sdv[4];
#pragma unroll
        for (int h = 0; h < NH; h++) {
            float ss = 0.f, sd = 0.f;
#pragma unroll
            for (int o = 0; o < NO; o++) {
                float wv = sm[t][h * 8 + o];
                ss = fmaf(wv, __ldg(av + h * 16 + o), ss);
                sd = fmaf(wv, __ldg(av + h * 16 + 8 + o), sd);
            }
            ssv[h] = ss; sdv[h] = sd;
        }
        *(float4*)&g_ssrc4[ii * 4] = make_float4(ssv[0], ssv[1], ssv[2], ssv[3]);
        *(float4*)&g_sdst4[ii * 4] = make_float4(sdv[0], sdv[1], sdv[2], sdv[3]);
        float m[4] = { sdv[0], sdv[1], sdv[2], sdv[3] };
#pragma unroll
        for (int off = 8; off > 0; off >>= 1) {
#pragma unroll
            for (int h = 0; h < 4; h++)
                m[h] = fmaxf(m[h], __shfl_xor_sync(0x0000ffffu, m[h], off));
        }
        if (t == 0) {
#pragma unroll
            for (int h = 0; h < 4; h++) atomicMax(&g_maxsd[h], fkey(m[h]));
        }
    }
}

// ---------------- 4) attention: 64 i per warp, 2 passes over head pairs ----------------
__global__ void __launch_bounds__(128, 5) k_attn() {
    __shared__ float s_wh[64 * 16];   // 4KB: pass head-pair Wh, [j][o*2+e]
    __shared__ float s_sd[64 * 4];    // 1KB: (sdl0, sdk0, sdl1, sdk1) per j
    int lane = threadIdx.x & 31, w = threadIdx.x >> 5;
    int ia = blockIdx.x * 256 + w * 64 + lane;
    int ib = ia + 32;
    int g = blockIdx.y >> 1;
    int lhalf = (blockIdx.y & 1) * 16;
    int j0 = g * 128 + (blockIdx.y & 1) * 64;

    float zA[4], zB[4];

#pragma unroll 1
    for (int hp = 0; hp < 2; hp++) {
        int h0 = hp * 2;
        __syncthreads();
#pragma unroll
        for (int q = 0; q < 2; q++) {
            int f = q * 128 + threadIdx.x;
            int j = f >> 2, cc = (f & 3) * 4;
            *(float4*)&s_wh[j * 16 + cc] =
                *(const float4*)&g_Wh[(size_t)(j0 + j) * NC32 + hp * 16 + cc];
        }
        if (threadIdx.x < 64) {
            float4 sd = ((const float4*)g_sdst4)[j0 + threadIdx.x];
            float a0 = hp ? sd.z : sd.x;
            float b0 = hp ? sd.w : sd.y;
            *(float4*)&s_sd[threadIdx.x * 4] =
                make_float4(a0 * L2E, a0 * KA, b0 * L2E, b0 * KA);
        }
        // per-pass scale factors (recomputed to cut register pressure)
        float M0 = funkey(g_maxsd[h0]);
        float M1 = funkey(g_maxsd[h0 + 1]);
        float2 ssa = *(const float2*)&g_ssrc4[ia * 4 + h0];
        float2 ssb = *(const float2*)&g_ssrc4[ib * 4 + h0];
        float ea0 = ssa.x + M0; ea0 = fmaxf(ea0, GAT_ALPHA * ea0);
        float ea1 = ssa.y + M1; ea1 = fmaxf(ea1, GAT_ALPHA * ea1);
        float eb0 = ssb.x + M0; eb0 = fmaxf(eb0, GAT_ALPHA * eb0);
        float eb1 = ssb.y + M1; eb1 = fmaxf(eb1, GAT_ALPHA * eb1);
        float sa0 = fmaf(ssa.x, L2E, -ea0 * L2E), ka0 = fmaf(ssa.x, KA, -ea0 * L2E);
        float sa1 = fmaf(ssa.y, L2E, -ea1 * L2E), ka1 = fmaf(ssa.y, KA, -ea1 * L2E);
        float sb0 = fmaf(ssb.x, L2E, -eb0 * L2E), kb0 = fmaf(ssb.x, KA, -eb0 * L2E);
        float sb1 = fmaf(ssb.y, L2E, -eb1 * L2E), kb1 = fmaf(ssb.y, KA, -eb1 * L2E);
        __syncthreads();

        unsigned long long accA[8], accB[8], zpA = 0ull, zpB = 0ull;
#pragma unroll
        for (int m = 0; m < 8; m++) { accA[m] = 0ull; accB[m] = 0ull; }

#pragma unroll
        for (int q = 0; q < 4; q++) {
            unsigned wa = g_bmT[(size_t)(g * 4 + q) * NN + ia] >> lhalf;
            unsigned wb = g_bmT[(size_t)(g * 4 + q) * NN + ib] >> lhalf;
#pragma unroll 8
            for (int l = 0; l < 16; l++) {
                int jj = l * 4 + q;
                float4 sd = *(const float4*)&s_sd[jj * 4];
                float wt0a = ex2f(fmaxf(sd.x + sa0, sd.y + ka0));
                float wt1a = ex2f(fmaxf(sd.z + sa1, sd.w + ka1));
                float wt0b = ex2f(fmaxf(sd.x + sb0, sd.y + kb0));
                float wt1b = ex2f(fmaxf(sd.z + sb1, sd.w + kb1));
                bool oa = (wa >> l) & 1u;
                bool ob = (wb >> l) & 1u;
                wt0a = oa ? wt0a : 0.f;  wt1a = oa ? wt1a : 0.f;
                wt0b = ob ? wt0b : 0.f;  wt1b = ob ? wt1b : 0.f;
                unsigned long long wpa = packab(wt0a, wt1a);
                unsigned long long wpb = packab(wt0b, wt1b);
                addf2(zpA, wpa);
                addf2(zpB, wpb);
                const ulonglong2* wp = (const ulonglong2*)&s_wh[jj * 16];
                ulonglong2 q0 = wp[0], q1 = wp[1], q2 = wp[2], q3 = wp[3];
                ffma2(accA[0], wpa, q0.x); ffma2(accA[1], wpa, q0.y);
                ffma2(accA[2], wpa, q1.x); ffma2(accA[3], wpa, q1.y);
                ffma2(accA[4], wpa, q2.x); ffma2(accA[5], wpa, q2.y);
                ffma2(accA[6], wpa, q3.x); ffma2(accA[7], wpa, q3.y);
                ffma2(accB[0], wpb, q0.x); ffma2(accB[1], wpb, q0.y);
                ffma2(accB[2], wpb, q1.x); ffma2(accB[3], wpb, q1.y);
                ffma2(accB[4], wpb, q2.x); ffma2(accB[5], wpb, q2.y);
                ffma2(accB[6], wpb, q3.x); ffma2(accB[7], wpb, q3.y);
            }
        }
        {
            U64F2 u[8];
#pragma unroll
            for (int m = 0; m < 8; m++) u[m].u = accA[m];
            float* pa = g_hp + (size_t)ia * NC32 + h0 * 8;
            red4(pa,      u[0].f.x, u[1].f.x, u[2].f.x, u[3].f.x);
            red4(pa + 4,  u[4].f.x, u[5].f.x, u[6].f.x, u[7].f.x);
            red4(pa + 8,  u[0].f.y, u[1].f.y, u[2].f.y, u[3].f.y);
            red4(pa + 12, u[4].f.y, u[5].f.y, u[6].f.y, u[7].f.y);
#pragma unroll
            for (int m = 0; m < 8; m++) u[m].u = accB[m];
            float* pb = g_hp + (size_t)ib * NC32 + h0 * 8;
            red4(pb,      u[0].f.x, u[1].f.x, u[2].f.x, u[3].f.x);
            red4(pb + 4,  u[4].f.x, u[5].f.x, u[6].f.x, u[7].f.x);
            red4(pb + 8,  u[0].f.y, u[1].f.y, u[2].f.y, u[3].f.y);
            red4(pb + 12, u[4].f.y, u[5].f.y, u[6].f.y, u[7].f.y);
        }
        U64F2 za, zb; za.u = zpA; zb.u = zpB;
        zA[h0] = za.f.x; zA[h0 + 1] = za.f.y;
        zB[h0] = zb.f.x; zB[h0 + 1] = zb.f.y;
    }
    red4(g_z + (size_t)ia * 4, zA[0], zA[1], zA[2], zA[3]);
    red4(g_z + (size_t)ib * 4, zB[0], zB[1], zB[2], zB[3]);
}

// ---------------- 5) normalize, mean over heads, log_softmax; seed bias ----------------
__global__ void k_fin1(float* __restrict__ dne, int write_ne,
                       float* __restrict__ dout, int write_out,
                       const float* __restrict__ bl) {
    int i = blockIdx.x * 64 + threadIdx.x;    // grid 64, block 64
    if (blockIdx.x == 0 && threadIdx.x < 8 && write_out)
        dout[threadIdx.x] = __ldg(bl);        // seed bias for k_fin2 atomics
    float4 z4 = *(const float4*)&g_z[i * 4];
    float zi[4] = { 0.25f / fmaxf(z4.x, 1e-30f), 0.25f / fmaxf(z4.y, 1e-30f),
                    0.25f / fmaxf(z4.z, 1e-30f), 0.25f / fmaxf(z4.w, 1e-30f) };
    float ne[8];
#pragma unroll
    for (int o = 0; o < 8; o++) ne[o] = 0.f;
#pragma unroll
    for (int h = 0; h < 4; h++) {
        float4 p0 = *(const float4*)&g_hp[(size_t)i * NC32 + h * 8];
        float4 p1 = *(const float4*)&g_hp[(size_t)i * NC32 + h * 8 + 4];
        ne[0] = fmaf(p0.x, zi[h], ne[0]); ne[1] = fmaf(p0.y, zi[h], ne[1]);
        ne[2] = fmaf(p0.z, zi[h], ne[2]); ne[3] = fmaf(p0.w, zi[h], ne[3]);
        ne[4] = fmaf(p1.x, zi[h], ne[4]); ne[5] = fmaf(p1.y, zi[h], ne[5]);
        ne[6] = fmaf(p1.z, zi[h], ne[6]); ne[7] = fmaf(p1.w, zi[h], ne[7]);
    }
    float m = ne[0];
#pragma unroll
    for (int o = 1; o < 8; o++) m = fmaxf(m, ne[o]);
    float sum = 0.f;
#pragma unroll
    for (int o = 0; o < 8; o++) sum += expf(ne[o] - m);
    float lse = logf(sum) + m;
#pragma unroll
    for (int o = 0; o < 8; o++) g_ls[(size_t)i * NO + o] = ne[o] - lse;
    if (write_ne) {
#pragma unroll
        for (int o = 0; o < 8; o++) dne[(size_t)i * NO + o] = ne[o];
    }
}

// ---------------- 6) out = ls.T @ w_lin.T + b  (8 blocks, atomic finish) ----------------
__global__ void k_fin2(const float* __restrict__ wl, float* __restrict__ dout,
                       int write_out) {
    __shared__ float rb[256][8];
    int t = threadIdx.x;
    int i0 = blockIdx.x * 512;
    float p[8];
#pragma unroll
    for (int o = 0; o < 8; o++) p[o] = 0.f;
#pragma unroll
    for (int q = 0; q < 2; q++) {
        int i = i0 + q * 256 + t;
        float wv = __ldg(wl + i);
        float4 l0 = *(const float4*)&g_ls[(size_t)i * NO];
        float4 l1 = *(const float4*)&g_ls[(size_t)i * NO + 4];
        p[0] = fmaf(l0.x, wv, p[0]); p[1] = fmaf(l0.y, wv, p[1]);
        p[2] = fmaf(l0.z, wv, p[2]); p[3] = fmaf(l0.w, wv, p[3]);
        p[4] = fmaf(l1.x, wv, p[4]); p[5] = fmaf(l1.y, wv, p[5]);
        p[6] = fmaf(l1.z, wv, p[6]); p[7] = fmaf(l1.w, wv, p[7]);
    }
#pragma unroll
    for (int o = 0; o < 8; o++) rb[t][o] = p[o];
    __syncthreads();
    if (t < 8 && write_out) {
        float s = 0.f;
        for (int q = 0; q < 256; q++) s += rb[q][t];
        atomicAdd(&dout[t], s);
    }
}

// ---------------- launch ----------------
extern "C" void kernel_launch(void* const* d_in, const int* in_sizes, int n_in,
                              void* d_out, int out_size) {
    const float* x   = (const float*)d_in[0];
    const int*   adj = (const int*)d_in[1];
    const float* W   = (const float*)d_in[2];
    const float* a   = (const float*)d_in[3];
    const float* wl  = (const float*)d_in[4];
    const float* bl  = (const float*)d_in[5];
    float* outp = (float*)d_out;

    int write_out = 0, write_ne = 0, ne_off = 0;
    if (out_size >= 8 + NN * NO)      { write_out = 1; write_ne = 1; ne_off = 8; }
    else if (out_size == NN * NO)     { write_ne = 1; ne_off = 0; }
    else                              { write_out = 1; }

    k_pack<<<NN / 4, 128>>>(adj);
    dim3 gg(NN / 128, GKS);
    k_gemm<<<gg, 256>>>(x, W);
    k_whfin<<<NN / 16, 128>>>(a);
    dim3 ga(NN / 256, JS);
    k_attn<<<ga, 128>>>();
    k_fin1<<<NN / 64, 64>>>(outp + ne_off, write_ne, outp, write_out, bl);
    k_fin2<<<8, 256>>>(wl, outp, write_out);
}

// round 11
// speedup vs baseline: 1.0594x; 1.0594x over previous
#include <cuda_runtime.h>
#include <math.h>

#define NN 4096
#define NF 4096
#define NH 4
#define NO 8
#define NC32 32            // NH*NO
#define NW (NN/32)         // bitmask words per row = 128
#define JS 64              // attention j-splits (grid.y): 64 j per block
#define GKS 32             // k-splits for gemm
#define GAT_ALPHA 0.2f
#define L2E 1.44269504088896341f
#define KA  0.28853900817792683f   // 0.2 * log2(e)

// ---------------- scratch (__device__ globals; no allocations) ----------------
__device__ float         g_Cpart[GKS][NN * NC32]; // k-split GEMM partials (16MB)
__device__ float         g_Wh[NN * NC32];         // Wh interleaved: [i*32 + hp*16 + o*2 + (h&1)]
__device__ float         g_sdst4[NN * NH];        // s_dst[j][h]
__device__ float         g_ssrc4[NN * NH];        // s_src[i][h]
__device__ unsigned      g_bmT[NW * NN];          // bitmask: word g*4+q, bit l <-> j=g*128+4l+q
__device__ unsigned      g_maxsd[NH];             // global max of s_dst per head (keyed)
__device__ float         g_hp[NN * NC32];         // red-accumulated h' numerator (1MB)
__device__ float         g_z[NN * NH];            // red-accumulated Z
__device__ float         g_ls[NN * NO];           // log_softmax(node_embeddings)

// ---------------- helpers ----------------
__device__ __forceinline__ void ffma2(unsigned long long& d, unsigned long long a,
                                      unsigned long long b) {
    asm("fma.rn.f32x2 %0, %1, %2, %0;" : "+l"(d) : "l"(a), "l"(b));
}
__device__ __forceinline__ void addf2(unsigned long long& d, unsigned long long a) {
    asm("add.rn.f32x2 %0, %0, %1;" : "+l"(d) : "l"(a));
}
__device__ __forceinline__ unsigned long long packab(float a, float b) {
    unsigned long long r;
    asm("mov.b64 %0, {%1, %2};" : "=l"(r) : "f"(a), "f"(b));
    return r;
}
__device__ __forceinline__ unsigned long long pack2(float v) {
    unsigned long long r;
    asm("mov.b64 %0, {%1, %1};" : "=l"(r) : "f"(v));
    return r;
}
__device__ __forceinline__ float ex2f(float x) {
    float r;
    asm("ex2.approx.ftz.f32 %0, %1;" : "=f"(r) : "f"(x));
    return r;
}
__device__ __forceinline__ void red4(float* p, float a, float b, float c, float d) {
    asm volatile("red.global.add.v4.f32 [%0], {%1, %2, %3, %4};"
                 :: "l"(p), "f"(a), "f"(b), "f"(c), "f"(d) : "memory");
}
union U64F2 { unsigned long long u; float2 f; };

__device__ __forceinline__ unsigned fkey(float f) {
    unsigned u = __float_as_uint(f);
    return (u & 0x80000000u) ? ~u : (u | 0x80000000u);
}
__device__ __forceinline__ float funkey(unsigned k) {
    return __uint_as_float((k & 0x80000000u) ? (k & 0x7FFFFFFFu) : ~k);
}

// ---------------- 1) pack adjacency (int4 + 4 ballots, permuted bits) ----------------
// grid 1024 x 128.  word g*4+q, bit l  <->  adj[i][g*128 + l*4 + q]
__global__ void k_pack(const int* __restrict__ adj) {
    int t = threadIdx.x;
    int gt = blockIdx.x * 128 + t;                    // 1024*128 = NN*NC32
    g_hp[gt] = 0.f;
    if (gt < NN * NH) g_z[gt] = 0.f;
    if (gt < NH) g_maxsd[gt] = 0u;

    int w = t >> 5, lane = t & 31;
    int i = blockIdx.x * 4 + w;
    const int4* row = (const int4*)(adj + (size_t)i * NN);
#pragma unroll 8
    for (int g = 0; g < 32; g++) {                    // 32 groups of 128 j
        int4 v = __ldg(row + g * 32 + lane);          // j = g*128 + lane*4 + {0..3}
        unsigned b0 = __ballot_sync(0xffffffffu, v.x != 0);
        unsigned b1 = __ballot_sync(0xffffffffu, v.y != 0);
        unsigned b2 = __ballot_sync(0xffffffffu, v.z != 0);
        unsigned b3 = __ballot_sync(0xffffffffu, v.w != 0);
        if (lane == 0) {
            g_bmT[(size_t)(g * 4 + 0) * NN + i] = b0;
            g_bmT[(size_t)(g * 4 + 1) * NN + i] = b1;
            g_bmT[(size_t)(g * 4 + 2) * NN + i] = b2;
            g_bmT[(size_t)(g * 4 + 3) * NN + i] = b3;
        }
    }
}

// ---------------- 2) Wh = x @ Wc  (BM=256, 8x4 per thread, k-split x32) ----------------
__global__ void __launch_bounds__(256, 3) k_gemm(const float* __restrict__ x,
                                                 const float* __restrict__ W) {
    __shared__ float xs[256 * 36];
    __shared__ float ws[32][36];
    int t = threadIdx.x;
    int c4g = t & 7;           // 4-col group (cols c4g*4..+3)
    int rg = t >> 3;           // 8-row group (rows rg*8..+7)
    int row0 = blockIdx.x * 256;
    int kbase = blockIdx.y * (NF / GKS);   // 128 k per block

    unsigned long long acc01[8], acc23[8];
#pragma unroll
    for (int r = 0; r < 8; r++) { acc01[r] = 0ull; acc23[r] = 0ull; }

    for (int kt = 0; kt < NF / GKS; kt += 32) {
        int k0 = kbase + kt;
#pragma unroll
        for (int q = 0; q < 8; q++) {
            int f = q * 256 + t;
            int row = f >> 3, kq = f & 7;
            float4 v = __ldg((const float4*)(x + (size_t)(row0 + row) * NF + k0 + kq * 4));
            *(float4*)&xs[row * 36 + kq * 4] = v;
        }
        {
            int k = t >> 3, c4 = (t & 7) * 4;
            int h = c4 >> 3, o = c4 & 7;
            float4 v = __ldg((const float4*)(W + (size_t)h * NF * NO + (size_t)(k0 + k) * NO + o));
            *(float4*)&ws[k][c4] = v;
        }
        __syncthreads();
#pragma unroll
        for (int kk = 0; kk < 8; kk++) {
            float4 w0 = *(const float4*)&ws[kk * 4 + 0][c4g * 4];
            float4 w1 = *(const float4*)&ws[kk * 4 + 1][c4g * 4];
            float4 w2 = *(const float4*)&ws[kk * 4 + 2][c4g * 4];
            float4 w3 = *(const float4*)&ws[kk * 4 + 3][c4g * 4];
            unsigned long long w01_0 = packab(w0.x, w0.y), w23_0 = packab(w0.z, w0.w);
            unsigned long long w01_1 = packab(w1.x, w1.y), w23_1 = packab(w1.z, w1.w);
            unsigned long long w01_2 = packab(w2.x, w2.y), w23_2 = packab(w2.z, w2.w);
            unsigned long long w01_3 = packab(w3.x, w3.y), w23_3 = packab(w3.z, w3.w);
#pragma unroll
            for (int r = 0; r < 8; r++) {
                float4 xv = *(const float4*)&xs[(rg * 8 + r) * 36 + kk * 4];
                unsigned long long a0 = pack2(xv.x), a1 = pack2(xv.y);
                unsigned long long a2 = pack2(xv.z), a3 = pack2(xv.w);
                ffma2(acc01[r], a0, w01_0); ffma2(acc23[r], a0, w23_0);
                ffma2(acc01[r], a1, w01_1); ffma2(acc23[r], a1, w23_1);
                ffma2(acc01[r], a2, w01_2); ffma2(acc23[r], a2, w23_2);
                ffma2(acc01[r], a3, w01_3); ffma2(acc23[r], a3, w23_3);
            }
        }
        __syncthreads();
    }
    float* outp = g_Cpart[blockIdx.y];
#pragma unroll
    for (int r = 0; r < 8; r++) {
        U64F2 a, b; a.u = acc01[r]; b.u = acc23[r];
        *(float4*)&outp[(size_t)(row0 + rg * 8 + r) * NC32 + c4g * 4] =
            make_float4(a.f.x, a.f.y, b.f.x, b.f.y);
    }
}

// ---------------- 3) reduce k-splits; interleaved Wh; s_src/s_dst; sd max ----------------
// grid 256 x 128: 16 rows per block
__global__ void k_whfin(const float* __restrict__ av) {
    __shared__ float sm[16][36];
    int t = threadIdx.x;
    int rl = t >> 3;          // local row 0..15
    int c4 = t & 7;           // float4 column group
    int i = blockIdx.x * 16 + rl;

    float4 s = make_float4(0.f, 0.f, 0.f, 0.f);
#pragma unroll
    for (int ks = 0; ks < GKS; ks++) {
        float4 p = *(const float4*)&g_Cpart[ks][(size_t)i * NC32 + c4 * 4];
        s.x += p.x; s.y += p.y; s.z += p.z; s.w += p.w;
    }
    *(float4*)&sm[rl][c4 * 4] = s;
    __syncthreads();

    // interleaved Wh write
    {
        int hp = c4 >> 2, k4 = c4 & 3;
        float4 o;
        o.x = sm[rl][hp * 16 + 2 * k4];
        o.y = sm[rl][hp * 16 + 8 + 2 * k4];
        o.z = sm[rl][hp * 16 + 2 * k4 + 1];
        o.w = sm[rl][hp * 16 + 8 + 2 * k4 + 1];
        *(float4*)&g_Wh[(size_t)i * NC32 + hp * 16 + k4 * 4] = o;
    }

    if (t < 16) {
        int ii = blockIdx.x * 16 + t;
        float ssv[4], sdv[4];
#pragma unroll
        for (int h = 0; h < NH; h++) {
            float ss = 0.f, sd = 0.f;
#pragma unroll
            for (int o = 0; o < NO; o++) {
                float wv = sm[t][h * 8 + o];
                ss = fmaf(wv, __ldg(av + h * 16 + o), ss);
                sd = fmaf(wv, __ldg(av + h * 16 + 8 + o), sd);
            }
            ssv[h] = ss; sdv[h] = sd;
        }
        *(float4*)&g_ssrc4[ii * 4] = make_float4(ssv[0], ssv[1], ssv[2], ssv[3]);
        *(float4*)&g_sdst4[ii * 4] = make_float4(sdv[0], sdv[1], sdv[2], sdv[3]);
        float m[4] = { sdv[0], sdv[1], sdv[2], sdv[3] };
#pragma unroll
        for (int off = 8; off > 0; off >>= 1) {
#pragma unroll
            for (int h = 0; h < 4; h++)
                m[h] = fmaxf(m[h], __shfl_xor_sync(0x0000ffffu, m[h], off));
        }
        if (t == 0) {
#pragma unroll
            for (int h = 0; h < 4; h++) atomicMax(&g_maxsd[h], fkey(m[h]));
        }
    }
}

// ---------------- 4) attention: 64 i per warp, 2 passes over head pairs ----------------
__global__ void __launch_bounds__(128, 5) k_attn() {
    __shared__ float s_wh[64 * 16];   // 4KB: pass head-pair Wh, [j][o*2+e]
    __shared__ float s_sd[64 * 4];    // 1KB: (sdl0, sdk0, sdl1, sdk1) per j
    int lane = threadIdx.x & 31, w = threadIdx.x >> 5;
    int ia = blockIdx.x * 256 + w * 64 + lane;
    int ib = ia + 32;
    int g = blockIdx.y >> 1;
    int lhalf = (blockIdx.y & 1) * 16;
    int j0 = g * 128 + (blockIdx.y & 1) * 64;

    float zA[4], zB[4];

#pragma unroll 1
    for (int hp = 0; hp < 2; hp++) {
        int h0 = hp * 2;
        __syncthreads();
#pragma unroll
        for (int q = 0; q < 2; q++) {
            int f = q * 128 + threadIdx.x;
            int j = f >> 2, cc = (f & 3) * 4;
            *(float4*)&s_wh[j * 16 + cc] =
                *(const float4*)&g_Wh[(size_t)(j0 + j) * NC32 + hp * 16 + cc];
        }
        if (threadIdx.x < 64) {
            float4 sd = ((const float4*)g_sdst4)[j0 + threadIdx.x];
            float a0 = hp ? sd.z : sd.x;
            float b0 = hp ? sd.w : sd.y;
            *(float4*)&s_sd[threadIdx.x * 4] =
                make_float4(a0 * L2E, a0 * KA, b0 * L2E, b0 * KA);
        }
        // per-pass scale factors (recomputed to cut register pressure)
        float M0 = funkey(g_maxsd[h0]);
        float M1 = funkey(g_maxsd[h0 + 1]);
        float2 ssa = *(const float2*)&g_ssrc4[ia * 4 + h0];
        float2 ssb = *(const float2*)&g_ssrc4[ib * 4 + h0];
        float ea0 = ssa.x + M0; ea0 = fmaxf(ea0, GAT_ALPHA * ea0);
        float ea1 = ssa.y + M1; ea1 = fmaxf(ea1, GAT_ALPHA * ea1);
        float eb0 = ssb.x + M0; eb0 = fmaxf(eb0, GAT_ALPHA * eb0);
        float eb1 = ssb.y + M1; eb1 = fmaxf(eb1, GAT_ALPHA * eb1);
        float sa0 = fmaf(ssa.x, L2E, -ea0 * L2E), ka0 = fmaf(ssa.x, KA, -ea0 * L2E);
        float sa1 = fmaf(ssa.y, L2E, -ea1 * L2E), ka1 = fmaf(ssa.y, KA, -ea1 * L2E);
        float sb0 = fmaf(ssb.x, L2E, -eb0 * L2E), kb0 = fmaf(ssb.x, KA, -eb0 * L2E);
        float sb1 = fmaf(ssb.y, L2E, -eb1 * L2E), kb1 = fmaf(ssb.y, KA, -eb1 * L2E);
        __syncthreads();

        unsigned long long accA[8], accB[8], zpA = 0ull, zpB = 0ull;
#pragma unroll
        for (int m = 0; m < 8; m++) { accA[m] = 0ull; accB[m] = 0ull; }

#pragma unroll
        for (int q = 0; q < 4; q++) {
            unsigned wa = g_bmT[(size_t)(g * 4 + q) * NN + ia] >> lhalf;
            unsigned wb = g_bmT[(size_t)(g * 4 + q) * NN + ib] >> lhalf;
#pragma unroll 8
            for (int l = 0; l < 16; l++) {
                int jj = l * 4 + q;
                float4 sd = *(const float4*)&s_sd[jj * 4];
                float wt0a = ex2f(fmaxf(sd.x + sa0, sd.y + ka0));
                float wt1a = ex2f(fmaxf(sd.z + sa1, sd.w + ka1));
                float wt0b = ex2f(fmaxf(sd.x + sb0, sd.y + kb0));
                float wt1b = ex2f(fmaxf(sd.z + sb1, sd.w + kb1));
                bool oa = (wa >> l) & 1u;
                bool ob = (wb >> l) & 1u;
                wt0a = oa ? wt0a : 0.f;  wt1a = oa ? wt1a : 0.f;
                wt0b = ob ? wt0b : 0.f;  wt1b = ob ? wt1b : 0.f;
                unsigned long long wpa = packab(wt0a, wt1a);
                unsigned long long wpb = packab(wt0b, wt1b);
                addf2(zpA, wpa);
                addf2(zpB, wpb);
                const ulonglong2* wp = (const ulonglong2*)&s_wh[jj * 16];
                ulonglong2 q0 = wp[0], q1 = wp[1], q2 = wp[2], q3 = wp[3];
                ffma2(accA[0], wpa, q0.x); ffma2(accA[1], wpa, q0.y);
                ffma2(accA[2], wpa, q1.x); ffma2(accA[3], wpa, q1.y);
                ffma2(accA[4], wpa, q2.x); ffma2(accA[5], wpa, q2.y);
                ffma2(accA[6], wpa, q3.x); ffma2(accA[7], wpa, q3.y);
                ffma2(accB[0], wpb, q0.x); ffma2(accB[1], wpb, q0.y);
                ffma2(accB[2], wpb, q1.x); ffma2(accB[3], wpb, q1.y);
                ffma2(accB[4], wpb, q2.x); ffma2(accB[5], wpb, q2.y);
                ffma2(accB[6], wpb, q3.x); ffma2(accB[7], wpb, q3.y);
            }
        }
        {
            U64F2 u[8];
#pragma unroll
            for (int m = 0; m < 8; m++) u[m].u = accA[m];
            float* pa = g_hp + (size_t)ia * NC32 + h0 * 8;
            red4(pa,      u[0].f.x, u[1].f.x, u[2].f.x, u[3].f.x);
            red4(pa + 4,  u[4].f.x, u[5].f.x, u[6].f.x, u[7].f.x);
            red4(pa + 8,  u[0].f.y, u[1].f.y, u[2].f.y, u[3].f.y);
            red4(pa + 12, u[4].f.y, u[5].f.y, u[6].f.y, u[7].f.y);
#pragma unroll
            for (int m = 0; m < 8; m++) u[m].u = accB[m];
            float* pb = g_hp + (size_t)ib * NC32 + h0 * 8;
            red4(pb,      u[0].f.x, u[1].f.x, u[2].f.x, u[3].f.x);
            red4(pb + 4,  u[4].f.x, u[5].f.x, u[6].f.x, u[7].f.x);
            red4(pb + 8,  u[0].f.y, u[1].f.y, u[2].f.y, u[3].f.y);
            red4(pb + 12, u[4].f.y, u[5].f.y, u[6].f.y, u[7].f.y);
        }
        U64F2 za, zb; za.u = zpA; zb.u = zpB;
        zA[h0] = za.f.x; zA[h0 + 1] = za.f.y;
        zB[h0] = zb.f.x; zB[h0 + 1] = zb.f.y;
    }
    red4(g_z + (size_t)ia * 4, zA[0], zA[1], zA[2], zA[3]);
    red4(g_z + (size_t)ib * 4, zB[0], zB[1], zB[2], zB[3]);
}

// ---------------- 5) normalize, mean over heads, log_softmax; seed bias ----------------
__global__ void k_fin1(float* __restrict__ dne, int write_ne,
                       float* __restrict__ dout, int write_out,
                       const float* __restrict__ bl) {
    int i = blockIdx.x * 64 + threadIdx.x;    // grid 64, block 64
    if (blockIdx.x == 0 && threadIdx.x < 8 && write_out)
        dout[threadIdx.x] = __ldg(bl);        // seed bias for k_fin2 atomics
    float4 z4 = *(const float4*)&g_z[i * 4];
    float zi[4] = { 0.25f / fmaxf(z4.x, 1e-30f), 0.25f / fmaxf(z4.y, 1e-30f),
                    0.25f / fmaxf(z4.z, 1e-30f), 0.25f / fmaxf(z4.w, 1e-30f) };
    float ne[8];
#pragma unroll
    for (int o = 0; o < 8; o++) ne[o] = 0.f;
#pragma unroll
    for (int h = 0; h < 4; h++) {
        float4 p0 = *(const float4*)&g_hp[(size_t)i * NC32 + h * 8];
        float4 p1 = *(const float4*)&g_hp[(size_t)i * NC32 + h * 8 + 4];
        ne[0] = fmaf(p0.x, zi[h], ne[0]); ne[1] = fmaf(p0.y, zi[h], ne[1]);
        ne[2] = fmaf(p0.z, zi[h], ne[2]); ne[3] = fmaf(p0.w, zi[h], ne[3]);
        ne[4] = fmaf(p1.x, zi[h], ne[4]); ne[5] = fmaf(p1.y, zi[h], ne[5]);
        ne[6] = fmaf(p1.z, zi[h], ne[6]); ne[7] = fmaf(p1.w, zi[h], ne[7]);
    }
    float m = ne[0];
#pragma unroll
    for (int o = 1; o < 8; o++) m = fmaxf(m, ne[o]);
    float sum = 0.f;
#pragma unroll
    for (int o = 0; o < 8; o++) sum += expf(ne[o] - m);
    float lse = logf(sum) + m;
#pragma unroll
    for (int o = 0; o < 8; o++) g_ls[(size_t)i * NO + o] = ne[o] - lse;
    if (write_ne) {
#pragma unroll
        for (int o = 0; o < 8; o++) dne[(size_t)i * NO + o] = ne[o];
    }
}

// ---------------- 6) out = ls.T @ w_lin.T + b  (8 blocks, atomic finish) ----------------
__global__ void k_fin2(const float* __restrict__ wl, float* __restrict__ dout,
                       int write_out) {
    __shared__ float rb[256][8];
    int t = threadIdx.x;
    int i0 = blockIdx.x * 512;
    float p[8];
#pragma unroll
    for (int o = 0; o < 8; o++) p[o] = 0.f;
#pragma unroll
    for (int q = 0; q < 2; q++) {
        int i = i0 + q * 256 + t;
        float wv = __ldg(wl + i);
        float4 l0 = *(const float4*)&g_ls[(size_t)i * NO];
        float4 l1 = *(const float4*)&g_ls[(size_t)i * NO + 4];
        p[0] = fmaf(l0.x, wv, p[0]); p[1] = fmaf(l0.y, wv, p[1]);
        p[2] = fmaf(l0.z, wv, p[2]); p[3] = fmaf(l0.w, wv, p[3]);
        p[4] = fmaf(l1.x, wv, p[4]); p[5] = fmaf(l1.y, wv, p[5]);
        p[6] = fmaf(l1.z, wv, p[6]); p[7] = fmaf(l1.w, wv, p[7]);
    }
#pragma unroll
    for (int o = 0; o < 8; o++) rb[t][o] = p[o];
    __syncthreads();
    if (t < 8 && write_out) {
        float s = 0.f;
        for (int q = 0; q < 256; q++) s += rb[q][t];
        atomicAdd(&dout[t], s);
    }
}

// ---------------- launch ----------------
extern "C" void kernel_launch(void* const* d_in, const int* in_sizes, int n_in,
                              void* d_out, int out_size) {
    const float* x   = (const float*)d_in[0];
    const int*   adj = (const int*)d_in[1];
    const float* W   = (const float*)d_in[2];
    const float* a   = (const float*)d_in[3];
    const float* wl  = (const float*)d_in[4];
    const float* bl  = (const float*)d_in[5];
    float* outp = (float*)d_out;

    int write_out = 0, write_ne = 0, ne_off = 0;
    if (out_size >= 8 + NN * NO)      { write_out = 1; write_ne = 1; ne_off = 8; }
    else if (out_size == NN * NO)     { write_ne = 1; ne_off = 0; }
    else                              { write_out = 1; }

    // fork a side stream so DRAM-bound k_pack overlaps compute-bound k_gemm.
    // kernel_launch runs only during correctness + capture (a few calls total),
    // so creating (and intentionally not destroying) these is benign and keeps
    // the captured graph valid. No device memory is allocated.
    cudaStream_t s1;
    cudaStreamCreateWithFlags(&s1, cudaStreamNonBlocking);
    cudaEvent_t e0, e1;
    cudaEventCreateWithFlags(&e0, cudaEventDisableTiming);
    cudaEventCreateWithFlags(&e1, cudaEventDisableTiming);

    cudaEventRecord(e0, 0);
    cudaStreamWaitEvent(s1, e0, 0);
    k_pack<<<NN / 4, 128, 0, s1>>>(adj);           // side stream
    cudaEventRecord(e1, s1);

    dim3 gg(NN / 256, GKS);
    k_gemm<<<gg, 256>>>(x, W);                      // main stream
    k_whfin<<<NN / 16, 128>>>(a);

    cudaStreamWaitEvent(0, e1, 0);                  // join before attention
    dim3 ga(NN / 256, JS);
    k_attn<<<ga, 128>>>();
    k_fin1<<<NN / 64, 64>>>(outp + ne_off, write_ne, outp, write_out, bl);
    k_fin2<<<8, 256>>>(wl, outp, write_out);
}